// round 5
// baseline (speedup 1.0000x reference)
#include <cuda_runtime.h>
#include <math.h>
#include <stdint.h>

#define NB 32
#define NL 8400
#define NC 80
#define NGT 64
#define KTOP 13
#define CAP 2048
#define NW 263              /* ceil(8400/32) */
#define MAXPOS (NB * NGT * KTOP)
#define FEPS 1e-9f
#define CEPS 1e-7f
#define BL (NB * NL)

// ---------------- device scratch (static zero-init; pipeline self-cleans) ----------------
__device__ unsigned long long g_ckey[(size_t)NB * NGT * CAP]; // row-sparse candidate keys
__device__ unsigned int g_cnt[NB * NGT];                      // per-row candidate counts
__device__ unsigned int g_colmax[BL];                         // per-anchor max iou bits
__device__ unsigned long long g_posmask[BL];                  // per-anchor positive gt bits
__device__ unsigned int g_rowmaxM[NB * NGT];                  // float bits, >=0
__device__ unsigned int g_rowmaxI[NB * NGT];
__device__ int g_poslist[MAXPOS];                             // compact positive anchors
__device__ unsigned int g_poscnt;

// ---- shared noinline math: ONE code body -> bit-identical across kernels ----
__device__ __noinline__ float atan_ratio(float w, float h) {
    return atanf(__fdividef(w, h));
}

__device__ __noinline__ float ciou_clip(float4 gb, float4 p, float gatan, float patan) {
    const float c4pi2 = 4.0f / (float)(M_PI * M_PI);
    float a1 = (gb.z - gb.x) * (gb.w - gb.y);
    float a2 = (p.z - p.x) * (p.w - p.y);
    float iw = fminf(gb.z, p.z) - fmaxf(gb.x, p.x);
    float ih = fminf(gb.w, p.w) - fmaxf(gb.y, p.y);
    float inter = fmaxf(iw, 0.f) * fmaxf(ih, 0.f);
    float uni = a1 + a2 - inter;
    float iou = __fdividef(inter, uni);
    float cw = fmaxf(fmaxf(gb.z, p.z) - fminf(gb.x, p.x), 0.f);
    float ch = fmaxf(fmaxf(gb.w, p.w) - fminf(gb.y, p.y), 0.f);
    float diag2 = cw * cw + ch * ch + CEPS;
    float dx = (gb.x + gb.z) * 0.5f - (p.x + p.z) * 0.5f;
    float dy = (gb.y + gb.w) * 0.5f - (p.y + p.w) * 0.5f;
    float diou = iou - __fdividef(dx * dx + dy * dy, diag2);
    float dv = gatan - patan;
    float v = c4pi2 * dv * dv;
    float ciou = diou - __fdividef(v * v, 1.f - iou + v + CEPS);
    return fmaxf(ciou, 0.f);
}

// ---------------- kernel 1: sparse candidate emission + per-anchor colmax ----------------
__global__ void __launch_bounds__(256) k_pair(
        const float* __restrict__ pred_scores,
        const float* __restrict__ pred_bboxes,
        const float* __restrict__ centers,
        const int* __restrict__ gt_labels,
        const float* __restrict__ gt_bboxes,
        const float* __restrict__ pad) {
    int b = blockIdx.y;
    int tid = threadIdx.x;
    int j = blockIdx.x * 256 + tid;
    int lane = tid & 31;
    unsigned lmask_lt = (1u << lane) - 1u;

    __shared__ float4 sbox[NGT];
    __shared__ int slab[NGT];
    __shared__ float satan[NGT];
    __shared__ int scnt;

    if (tid < NGT) {
        float4 gb = ((const float4*)gt_bboxes)[b * NGT + tid];
        sbox[tid] = gb;
        slab[tid] = gt_labels[b * NGT + tid];
        satan[tid] = atan_ratio(gb.z - gb.x, gb.w - gb.y);
    }
    if (tid == 0) {
        int c = 0;
        for (int i = 0; i < NGT; i++) c += (pad[b * NGT + i] != 0.f);
        scnt = c;
    }
    __syncthreads();

    int cnt = scnt;
    bool live = (j < NL);
    int jc = live ? j : (NL - 1);

    float2 ct = ((const float2*)centers)[jc];
    float4 p = ((const float4*)pred_bboxes)[(size_t)b * NL + jc];
    float patan = atan_ratio(p.z - p.x, p.w - p.y);
    const float* srow = pred_scores + ((size_t)b * NL + jc) * NC;

    float colmax = 0.f;
    for (int i = 0; i < cnt; i++) {
        float4 gb = sbox[i];
        float lt = fminf(fminf(ct.x - gb.x, ct.y - gb.y),
                         fminf(gb.z - ct.x, gb.w - ct.y));
        bool in = live && (lt > FEPS);
        unsigned m = __ballot_sync(0xFFFFFFFFu, in);
        if (!m) continue;
        unsigned long long key = 0ull;
        if (in) {
            float io = ciou_clip(gb, p, satan[i], patan);
            colmax = fmaxf(colmax, io);
            float score = __ldg(srow + slab[i]);
            float m2 = io * io;
            float m6 = m2 * m2 * m2;
            float metric = score * m6;
            key = ((unsigned long long)__float_as_uint(metric) << 32) |
                  (unsigned long long)(0xFFFFFFFFu - (unsigned)j);
        }
        int row = b * NGT + i;
        int leader = __ffs(m) - 1;
        unsigned base = 0;
        if (lane == leader) base = atomicAdd(&g_cnt[row], (unsigned)__popc(m));
        base = __shfl_sync(0xFFFFFFFFu, base, leader);
        if (in) {
            unsigned pos = base + (unsigned)__popc(m & lmask_lt);
            if (pos < CAP) g_ckey[(size_t)row * CAP + pos] = key;
        }
    }
    if (live) {
        int t = b * NL + j;
        g_colmax[t] = __float_as_uint(colmax);
        g_posmask[t] = 0ull;
    }
}

// ---------------- kernel 2: top-13 per row, emit bits + compact positive list ----------------
__global__ void __launch_bounds__(128) k_topk(const float* __restrict__ pad) {
    int gt = blockIdx.x;
    if (pad[gt] == 0.f) return;
    int b = gt >> 6;
    int i = gt & 63;
    int t = threadIdx.x;

    __shared__ unsigned long long sh[128][KTOP];
    __shared__ unsigned scand[NW];
    __shared__ unsigned szcand[NW];

    for (int w = t; w < NW; w += 128) { scand[w] = 0u; szcand[w] = 0u; }
    if (t == 0) {                       // self-clean rowmax for this row
        g_rowmaxM[gt] = 0u;
        g_rowmaxI[gt] = 0u;
    }
    __syncthreads();

    unsigned count = g_cnt[gt];
    if (count > CAP) count = CAP;
    const unsigned long long* keys = g_ckey + (size_t)gt * CAP;

    unsigned long long best[KTOP];
#pragma unroll
    for (int k = 0; k < KTOP; k++) best[k] = 0ull;

    for (unsigned c = t; c < count; c += 128) {
        unsigned long long key = keys[c];
        unsigned j = 0xFFFFFFFFu - (unsigned)(key & 0xFFFFFFFFull);
        atomicOr(&scand[j >> 5], 1u << (j & 31));
        if ((unsigned)(key >> 32) == 0u)
            atomicOr(&szcand[j >> 5], 1u << (j & 31));
        if (key > best[KTOP - 1]) {
            best[KTOP - 1] = key;
#pragma unroll
            for (int q = KTOP - 1; q > 0; q--) {
                if (best[q] > best[q - 1]) {
                    unsigned long long tmp = best[q - 1];
                    best[q - 1] = best[q]; best[q] = tmp;
                }
            }
        }
    }
#pragma unroll
    for (int k = 0; k < KTOP; k++) sh[t][k] = best[k];
    __syncthreads();

    for (int s = 64; s > 0; s >>= 1) {
        if (t < s) {
            unsigned long long tmp[KTOP];
            int a = 0, c = 0;
#pragma unroll
            for (int k = 0; k < KTOP; k++) {
                unsigned long long va = sh[t][a];
                unsigned long long vb = sh[t + s][c];
                if (va >= vb) { tmp[k] = va; a++; }
                else          { tmp[k] = vb; c++; }
            }
#pragma unroll
            for (int k = 0; k < KTOP; k++) sh[t][k] = tmp[k];
        }
        __syncthreads();
    }

    // positive-metric selections emit bits; first setter pushes anchor to list
    if (t < KTOP) {
        unsigned long long key = sh[0][t];
        if ((unsigned)(key >> 32) != 0u) {
            unsigned j = 0xFFFFFFFFu - (unsigned)(key & 0xFFFFFFFFull);
            int anc = b * NL + (int)j;
            unsigned long long old = atomicOr(&g_posmask[anc], 1ull << i);
            if (old == 0ull) {
                unsigned pos = atomicAdd(&g_poscnt, 1u);
                g_poslist[pos] = anc;
            }
        }
    }
    if (t == 0) g_cnt[gt] = 0u;         // self-clean candidate counter
    __syncthreads();

    if (t == 0) {
        int P = 0;
#pragma unroll
        for (int k = 0; k < KTOP; k++)
            if ((unsigned)(sh[0][k] >> 32) != 0u) P++;
        int need = KTOP - P;
        // jax fill: smallest indices with metric==0; only zero-metric candidates
        // (in_gts=1) contribute mask bits.
        for (int w = 0; w < NW && need > 0; w++) {
            unsigned zm = (~scand[w]) | szcand[w];
            if (w == NW - 1) zm &= 0xFFFFu;  // 8400 = 262*32 + 16
            while (zm && need > 0) {
                int bit = __ffs(zm) - 1;
                zm &= zm - 1;
                need--;
                if ((szcand[w] >> bit) & 1u) {
                    int anc = b * NL + w * 32 + bit;
                    unsigned long long old = atomicOr(&g_posmask[anc], 1ull << i);
                    if (old == 0ull) {
                        unsigned pos = atomicAdd(&g_poscnt, 1u);
                        g_poslist[pos] = anc;
                    }
                }
            }
        }
    }
}

// ---------------- kernel 3: fixup + rowmax over compact positive list ----------------
__global__ void __launch_bounds__(256) k_fix(
        const float* __restrict__ pred_scores,
        const float* __restrict__ pred_bboxes,
        const float* __restrict__ centers,
        const int* __restrict__ gt_labels,
        const float* __restrict__ gt_bboxes,
        const float* __restrict__ pad) {
    unsigned k = blockIdx.x * 256 + threadIdx.x;
    if (k >= g_poscnt) return;
    int t = g_poslist[k];
    int b = t / NL;
    int j = t - b * NL;

    unsigned long long pm = g_posmask[t];
    int s = __popcll(pm);

    float2 ct = ((const float2*)centers)[j];
    float4 p = ((const float4*)pred_bboxes)[(size_t)b * NL + j];
    float patan = atan_ratio(p.z - p.x, p.w - p.y);
    const float* srow = pred_scores + ((size_t)b * NL + j) * NC;

    if (s > 1) {
        float mx = __uint_as_float(g_colmax[t]);
        if (mx == 0.f) {
            pm = 1ull;              // all-zero column: argmax=0, zero terms downstream
        } else {
            int cnt = 0;
            for (int i = 0; i < NGT; i++) cnt += (pad[b * NGT + i] != 0.f);
            pm = 0ull;
            for (int i = 0; i < cnt; i++) {
                float4 gb = ((const float4*)gt_bboxes)[b * NGT + i];
                float lt = fminf(fminf(ct.x - gb.x, ct.y - gb.y),
                                 fminf(gb.z - ct.x, gb.w - ct.y));
                if (lt > FEPS) {
                    float gatan = atan_ratio(gb.z - gb.x, gb.w - gb.y);
                    float io = ciou_clip(gb, p, gatan, patan);
                    if (io == mx) pm |= 1ull << i;
                }
            }
        }
        g_posmask[t] = pm;
    }

    unsigned long long q = pm;
    while (q) {
        int i = __ffsll(q) - 1;
        q &= q - 1;
        float4 gb = ((const float4*)gt_bboxes)[b * NGT + i];
        float lt = fminf(fminf(ct.x - gb.x, ct.y - gb.y),
                         fminf(gb.z - ct.x, gb.w - ct.y));
        float io = 0.f, metric = 0.f;
        if (lt > FEPS) {
            float gatan = atan_ratio(gb.z - gb.x, gb.w - gb.y);
            io = ciou_clip(gb, p, gatan, patan);
            float score = __ldg(srow + gt_labels[b * NGT + i]);
            float m2 = io * io;
            float m6 = m2 * m2 * m2;
            metric = score * m6;
        }
        atomicMax(&g_rowmaxM[b * NGT + i], __float_as_uint(metric));
        atomicMax(&g_rowmaxI[b * NGT + i], __float_as_uint(io));
    }
}

// ---------------- kernel 4: all dense outputs (labels/bbox/fg/norm/scores) ----------------
__global__ void __launch_bounds__(256) k_out(
        const float* __restrict__ pred_scores,
        const float* __restrict__ pred_bboxes,
        const float* __restrict__ centers,
        const int* __restrict__ gt_labels,
        const float* __restrict__ gt_bboxes,
        float* __restrict__ out, int out_size) {
    int b = blockIdx.y;
    int tid = threadIdx.x;
    int j = blockIdx.x * 256 + tid;

    __shared__ float4 sbox[NGT];
    __shared__ int slab[NGT];
    __shared__ float satan[NGT];
    __shared__ float snrm[256];
    __shared__ int slabel[256];
    if (tid < NGT) {
        float4 gb = ((const float4*)gt_bboxes)[b * NGT + tid];
        sbox[tid] = gb;
        slab[tid] = gt_labels[b * NGT + tid];
        satan[tid] = atan_ratio(gb.z - gb.x, gb.w - gb.y);
    }
    if (blockIdx.x == 0 && blockIdx.y == 0 && tid == 0)
        g_poscnt = 0u;                  // self-clean for next launch
    __syncthreads();

    float nrm = 0.f;
    int lab = NC;
    int ag0 = 0, s = 0;
    if (j < NL) {
        int t = b * NL + j;
        unsigned long long pm = g_posmask[t];
        s = __popcll(pm);
        if (pm) {
            ag0 = __ffsll(pm) - 1;
            lab = slab[ag0];
            float2 ct = ((const float2*)centers)[j];
            float4 p = ((const float4*)pred_bboxes)[(size_t)b * NL + j];
            float patan = atan_ratio(p.z - p.x, p.w - p.y);
            const float* srow = pred_scores + ((size_t)b * NL + j) * NC;
            while (pm) {
                int i = __ffsll(pm) - 1;
                pm &= pm - 1;
                float4 gb = sbox[i];
                float lt = fminf(fminf(ct.x - gb.x, ct.y - gb.y),
                                 fminf(gb.z - ct.x, gb.w - ct.y));
                if (lt > FEPS) {
                    float io = ciou_clip(gb, p, satan[i], patan);
                    float score = __ldg(srow + slab[i]);
                    float m2 = io * io;
                    float m6 = m2 * m2 * m2;
                    float metric = score * m6;
                    float term = __fdividef(metric,
                                     __uint_as_float(g_rowmaxM[b * NGT + i]) + FEPS) *
                                 __uint_as_float(g_rowmaxI[b * NGT + i]);
                    nrm = fmaxf(nrm, term);
                }
            }
        }
        // scalar outputs
        if (t < out_size) out[t] = (float)lab;
        size_t bo = (size_t)BL + (size_t)t * 4;
        if (bo + 3 < (size_t)out_size)
            ((float4*)(out + BL))[t] = sbox[ag0];
        size_t fo = (size_t)85 * BL + t;
        if (fo < (size_t)out_size) out[fo] = (s > 0) ? 1.f : 0.f;
    }
    snrm[tid] = nrm;
    slabel[tid] = lab;
    __syncthreads();

    int j0 = blockIdx.x * 256;
    int nanch = NL - j0; if (nanch > 256) nanch = 256;
    if (nanch <= 0) return;
    size_t base = (size_t)5 * BL + ((size_t)b * NL + j0) * NC;
    int total4 = nanch * (NC / 4);
    float4* ob = (float4*)(out + base);
    for (int f = tid; f < total4; f += 256) {
        int a = f / (NC / 4);
        int c0 = (f % (NC / 4)) * 4;
        float4 w = {0.f, 0.f, 0.f, 0.f};
        int L = slabel[a];
        if (L >= c0 && L < c0 + 4) ((float*)&w)[L - c0] = snrm[a];
        if (base + (size_t)f * 4 + 3 < (size_t)out_size) ob[f] = w;
    }
}

// ---------------- launch ----------------
extern "C" void kernel_launch(void* const* d_in, const int* in_sizes, int n_in,
                              void* d_out, int out_size) {
    const float* pred_scores = (const float*)d_in[0];
    const float* pred_bboxes = (const float*)d_in[1];
    const float* centers     = (const float*)d_in[2];
    const int*   gt_labels   = (const int*)d_in[3];
    const float* gt_bboxes   = (const float*)d_in[4];
    const float* pad         = (const float*)d_in[5];
    float* out = (float*)d_out;

    dim3 grid2d((NL + 255) / 256, NB);
    k_pair<<<grid2d, 256>>>(pred_scores, pred_bboxes, centers,
                            gt_labels, gt_bboxes, pad);
    k_topk<<<NB * NGT, 128>>>(pad);
    k_fix<<<(MAXPOS + 255) / 256, 256>>>(pred_scores, pred_bboxes, centers,
                                         gt_labels, gt_bboxes, pad);
    k_out<<<grid2d, 256>>>(pred_scores, pred_bboxes, centers,
                           gt_labels, gt_bboxes, out, out_size);
}

// round 6
// speedup vs baseline: 1.4466x; 1.4466x over previous
#include <cuda_runtime.h>
#include <math.h>
#include <stdint.h>

#define NB 32
#define NL 8400
#define NC 80
#define NGT 64
#define KTOP 13
#define CAP 2048
#define NW 263              /* ceil(8400/32) */
#define NSEL (NB * NGT * KTOP)
#define FEPS 1e-9f
#define CEPS 1e-7f
#define BL (NB * NL)

// ---------------- device scratch (static zero-init; pipeline self-cleans) ----------------
__device__ unsigned long long g_ckey[(size_t)NB * NGT * CAP]; // row-sparse candidate keys
__device__ unsigned int g_cnt[NB * NGT];                      // per-row candidate counts
__device__ unsigned int g_colmax[BL];                         // per-anchor max iou bits
__device__ unsigned long long g_posmask[BL];                  // per-anchor positive gt bits
__device__ unsigned int g_rowmaxM[NB * NGT];                  // float bits, >=0
__device__ unsigned int g_rowmaxI[NB * NGT];
__device__ int g_selidx[NSEL];                                // anchor+1 per (row,k), 0=empty

// ---- shared noinline math: ONE code body -> bit-identical across kernels ----
__device__ __noinline__ float atan_ratio(float w, float h) {
    return atanf(__fdividef(w, h));
}

__device__ __noinline__ float ciou_clip(float4 gb, float4 p, float gatan, float patan) {
    const float c4pi2 = 4.0f / (float)(M_PI * M_PI);
    float a1 = (gb.z - gb.x) * (gb.w - gb.y);
    float a2 = (p.z - p.x) * (p.w - p.y);
    float iw = fminf(gb.z, p.z) - fmaxf(gb.x, p.x);
    float ih = fminf(gb.w, p.w) - fmaxf(gb.y, p.y);
    float inter = fmaxf(iw, 0.f) * fmaxf(ih, 0.f);
    float uni = a1 + a2 - inter;
    float iou = __fdividef(inter, uni);
    float cw = fmaxf(fmaxf(gb.z, p.z) - fminf(gb.x, p.x), 0.f);
    float ch = fmaxf(fmaxf(gb.w, p.w) - fminf(gb.y, p.y), 0.f);
    float diag2 = cw * cw + ch * ch + CEPS;
    float dx = (gb.x + gb.z) * 0.5f - (p.x + p.z) * 0.5f;
    float dy = (gb.y + gb.w) * 0.5f - (p.y + p.w) * 0.5f;
    float diou = iou - __fdividef(dx * dx + dy * dy, diag2);
    float dv = gatan - patan;
    float v = c4pi2 * dv * dv;
    float ciou = diou - __fdividef(v * v, 1.f - iou + v + CEPS);
    return fmaxf(ciou, 0.f);
}

// ---------------- kernel 1: sparse candidate emission + per-anchor colmax ----------------
__global__ void __launch_bounds__(256) k_pair(
        const float* __restrict__ pred_scores,
        const float* __restrict__ pred_bboxes,
        const float* __restrict__ centers,
        const int* __restrict__ gt_labels,
        const float* __restrict__ gt_bboxes,
        const float* __restrict__ pad) {
    int b = blockIdx.y;
    int tid = threadIdx.x;
    int j = blockIdx.x * 256 + tid;
    int lane = tid & 31;
    unsigned lmask_lt = (1u << lane) - 1u;

    __shared__ float4 sbox[NGT];
    __shared__ int slab[NGT];
    __shared__ float satan[NGT];
    __shared__ int scnt;

    if (tid < NGT) {
        float4 gb = ((const float4*)gt_bboxes)[b * NGT + tid];
        sbox[tid] = gb;
        slab[tid] = gt_labels[b * NGT + tid];
        satan[tid] = atan_ratio(gb.z - gb.x, gb.w - gb.y);
    }
    if (tid == 0) {
        int c = 0;
        for (int i = 0; i < NGT; i++) c += (pad[b * NGT + i] != 0.f);
        scnt = c;
    }
    __syncthreads();

    int cnt = scnt;
    bool live = (j < NL);
    int jc = live ? j : (NL - 1);

    float2 ct = ((const float2*)centers)[jc];
    float4 p = ((const float4*)pred_bboxes)[(size_t)b * NL + jc];
    float patan = atan_ratio(p.z - p.x, p.w - p.y);
    const float* srow = pred_scores + ((size_t)b * NL + jc) * NC;

    float colmax = 0.f;
    for (int i = 0; i < cnt; i++) {
        float4 gb = sbox[i];
        float lt = fminf(fminf(ct.x - gb.x, ct.y - gb.y),
                         fminf(gb.z - ct.x, gb.w - ct.y));
        bool in = live && (lt > FEPS);
        unsigned m = __ballot_sync(0xFFFFFFFFu, in);
        if (!m) continue;
        unsigned long long key = 0ull;
        if (in) {
            float io = ciou_clip(gb, p, satan[i], patan);
            colmax = fmaxf(colmax, io);
            float score = __ldg(srow + slab[i]);
            float m2 = io * io;
            float m6 = m2 * m2 * m2;
            float metric = score * m6;
            key = ((unsigned long long)__float_as_uint(metric) << 32) |
                  (unsigned long long)(0xFFFFFFFFu - (unsigned)j);
        }
        int row = b * NGT + i;
        int leader = __ffs(m) - 1;
        unsigned base = 0;
        if (lane == leader) base = atomicAdd(&g_cnt[row], (unsigned)__popc(m));
        base = __shfl_sync(0xFFFFFFFFu, base, leader);
        if (in) {
            unsigned pos = base + (unsigned)__popc(m & lmask_lt);
            if (pos < CAP) g_ckey[(size_t)row * CAP + pos] = key;
        }
    }
    if (live) {
        int t = b * NL + j;
        g_colmax[t] = __float_as_uint(colmax);
        g_posmask[t] = 0ull;
    }
}

// ---------------- kernel 2: top-13 per row -> posmask bits + per-row slot list ----------------
__global__ void __launch_bounds__(256) k_topk(const float* __restrict__ pad) {
    int gt = blockIdx.x;
    if (pad[gt] == 0.f) return;
    int b = gt >> 6;
    int i = gt & 63;
    int t = threadIdx.x;

    __shared__ unsigned long long sh[256][KTOP];
    __shared__ unsigned scand[NW];
    __shared__ unsigned szcand[NW];
    __shared__ int semit[KTOP];

    for (int w = t; w < NW; w += 256) { scand[w] = 0u; szcand[w] = 0u; }
    if (t == 0) {                       // self-clean rowmax for this row
        g_rowmaxM[gt] = 0u;
        g_rowmaxI[gt] = 0u;
    }
    __syncthreads();

    unsigned count = g_cnt[gt];
    if (count > CAP) count = CAP;
    const unsigned long long* keys = g_ckey + (size_t)gt * CAP;

    unsigned long long best[KTOP];
#pragma unroll
    for (int k = 0; k < KTOP; k++) best[k] = 0ull;

    for (unsigned c = t; c < count; c += 256) {
        unsigned long long key = keys[c];
        unsigned j = 0xFFFFFFFFu - (unsigned)(key & 0xFFFFFFFFull);
        atomicOr(&scand[j >> 5], 1u << (j & 31));
        if ((unsigned)(key >> 32) == 0u)
            atomicOr(&szcand[j >> 5], 1u << (j & 31));
        if (key > best[KTOP - 1]) {
            best[KTOP - 1] = key;
#pragma unroll
            for (int q = KTOP - 1; q > 0; q--) {
                if (best[q] > best[q - 1]) {
                    unsigned long long tmp = best[q - 1];
                    best[q - 1] = best[q]; best[q] = tmp;
                }
            }
        }
    }
#pragma unroll
    for (int k = 0; k < KTOP; k++) sh[t][k] = best[k];
    __syncthreads();

    for (int s = 128; s > 0; s >>= 1) {
        if (t < s) {
            unsigned long long tmp[KTOP];
            int a = 0, c = 0;
#pragma unroll
            for (int k = 0; k < KTOP; k++) {
                unsigned long long va = sh[t][a];
                unsigned long long vb = sh[t + s][c];
                if (va >= vb) { tmp[k] = va; a++; }
                else          { tmp[k] = vb; c++; }
            }
#pragma unroll
            for (int k = 0; k < KTOP; k++) sh[t][k] = tmp[k];
        }
        __syncthreads();
    }

    // positive-metric selections: posmask bits + slot entries
    if (t < KTOP) {
        unsigned long long key = sh[0][t];
        int sel = 0;
        if ((unsigned)(key >> 32) != 0u) {
            unsigned j = 0xFFFFFFFFu - (unsigned)(key & 0xFFFFFFFFull);
            int anc = b * NL + (int)j;
            atomicOr(&g_posmask[anc], 1ull << i);
            sel = anc + 1;
        }
        semit[t] = sel;
    }
    if (t == 0) g_cnt[gt] = 0u;         // self-clean candidate counter
    __syncthreads();

    if (t == 0) {
        // jax zero-fill: smallest indices with metric==0 (zero candidate OR
        // non-candidate); only zero-metric candidates (in_gts=1) emit bits.
        int need = 0;
#pragma unroll
        for (int k = 0; k < KTOP; k++) need += (semit[k] == 0);
        int slot = 0;
        for (int w = 0; w < NW && need > 0; w++) {
            unsigned zm = (~scand[w]) | szcand[w];
            if (w == NW - 1) zm &= 0xFFFFu;  // 8400 = 262*32 + 16
            while (zm && need > 0) {
                int bit = __ffs(zm) - 1;
                zm &= zm - 1;
                need--;
                if ((szcand[w] >> bit) & 1u) {
                    int anc = b * NL + w * 32 + bit;
                    atomicOr(&g_posmask[anc], 1ull << i);
                    while (semit[slot] != 0) slot++;
                    semit[slot] = anc + 1;
                }
            }
        }
    }
    __syncthreads();
    if (t < KTOP) g_selidx[gt * KTOP + t] = semit[t];
}

// ---------------- kernel 3: fixup + rowmax over selected anchors (dups harmless) ----------------
__global__ void __launch_bounds__(256) k_fix(
        const float* __restrict__ pred_scores,
        const float* __restrict__ pred_bboxes,
        const float* __restrict__ centers,
        const int* __restrict__ gt_labels,
        const float* __restrict__ gt_bboxes,
        const float* __restrict__ pad) {
    int k = blockIdx.x * 256 + threadIdx.x;
    if (k >= NSEL) return;
    int sel = g_selidx[k];
    if (sel == 0) return;
    int t = sel - 1;
    int b = t / NL;
    int j = t - b * NL;

    unsigned long long pm = g_posmask[t];
    int s = __popcll(pm);

    float2 ct = ((const float2*)centers)[j];
    float4 p = ((const float4*)pred_bboxes)[(size_t)b * NL + j];
    float patan = atan_ratio(p.z - p.x, p.w - p.y);
    const float* srow = pred_scores + ((size_t)b * NL + j) * NC;

    if (s > 1) {
        float mx = __uint_as_float(g_colmax[t]);
        if (mx == 0.f) {
            pm = 1ull;              // all-zero column: argmax=0, zero terms downstream
        } else {
            int cnt = 0;
            for (int i = 0; i < NGT; i++) cnt += (pad[b * NGT + i] != 0.f);
            pm = 0ull;
            for (int i = 0; i < cnt; i++) {
                float4 gb = ((const float4*)gt_bboxes)[b * NGT + i];
                float lt = fminf(fminf(ct.x - gb.x, ct.y - gb.y),
                                 fminf(gb.z - ct.x, gb.w - ct.y));
                if (lt > FEPS) {
                    float gatan = atan_ratio(gb.z - gb.x, gb.w - gb.y);
                    float io = ciou_clip(gb, p, gatan, patan);
                    if (io == mx) pm |= 1ull << i;
                }
            }
        }
        g_posmask[t] = pm;
    }

    unsigned long long q = pm;
    while (q) {
        int i = __ffsll(q) - 1;
        q &= q - 1;
        float4 gb = ((const float4*)gt_bboxes)[b * NGT + i];
        float lt = fminf(fminf(ct.x - gb.x, ct.y - gb.y),
                         fminf(gb.z - ct.x, gb.w - ct.y));
        float io = 0.f, metric = 0.f;
        if (lt > FEPS) {
            float gatan = atan_ratio(gb.z - gb.x, gb.w - gb.y);
            io = ciou_clip(gb, p, gatan, patan);
            float score = __ldg(srow + gt_labels[b * NGT + i]);
            float m2 = io * io;
            float m6 = m2 * m2 * m2;
            metric = score * m6;
        }
        atomicMax(&g_rowmaxM[b * NGT + i], __float_as_uint(metric));
        atomicMax(&g_rowmaxI[b * NGT + i], __float_as_uint(io));
    }
}

// ---------------- kernel 4: all dense outputs (labels/bbox/fg/norm/scores) ----------------
__global__ void __launch_bounds__(256) k_out(
        const float* __restrict__ pred_scores,
        const float* __restrict__ pred_bboxes,
        const float* __restrict__ centers,
        const int* __restrict__ gt_labels,
        const float* __restrict__ gt_bboxes,
        float* __restrict__ out, int out_size) {
    int b = blockIdx.y;
    int tid = threadIdx.x;
    int j = blockIdx.x * 256 + tid;

    __shared__ float4 sbox[NGT];
    __shared__ int slab[NGT];
    __shared__ float satan[NGT];
    __shared__ float snrm[256];
    __shared__ int slabel[256];
    if (tid < NGT) {
        float4 gb = ((const float4*)gt_bboxes)[b * NGT + tid];
        sbox[tid] = gb;
        slab[tid] = gt_labels[b * NGT + tid];
        satan[tid] = atan_ratio(gb.z - gb.x, gb.w - gb.y);
    }
    __syncthreads();

    float nrm = 0.f;
    int lab = NC;
    int ag0 = 0, s = 0;
    if (j < NL) {
        int t = b * NL + j;
        unsigned long long pm = g_posmask[t];
        s = __popcll(pm);
        if (pm) {
            ag0 = __ffsll(pm) - 1;
            lab = slab[ag0];
            float2 ct = ((const float2*)centers)[j];
            float4 p = ((const float4*)pred_bboxes)[(size_t)b * NL + j];
            float patan = atan_ratio(p.z - p.x, p.w - p.y);
            const float* srow = pred_scores + ((size_t)b * NL + j) * NC;
            while (pm) {
                int i = __ffsll(pm) - 1;
                pm &= pm - 1;
                float4 gb = sbox[i];
                float lt = fminf(fminf(ct.x - gb.x, ct.y - gb.y),
                                 fminf(gb.z - ct.x, gb.w - ct.y));
                if (lt > FEPS) {
                    float io = ciou_clip(gb, p, satan[i], patan);
                    float score = __ldg(srow + slab[i]);
                    float m2 = io * io;
                    float m6 = m2 * m2 * m2;
                    float metric = score * m6;
                    float term = __fdividef(metric,
                                     __uint_as_float(g_rowmaxM[b * NGT + i]) + FEPS) *
                                 __uint_as_float(g_rowmaxI[b * NGT + i]);
                    nrm = fmaxf(nrm, term);
                }
            }
        }
        // scalar outputs
        if (t < out_size) out[t] = (float)lab;
        size_t bo = (size_t)BL + (size_t)t * 4;
        if (bo + 3 < (size_t)out_size)
            ((float4*)(out + BL))[t] = sbox[ag0];
        size_t fo = (size_t)85 * BL + t;
        if (fo < (size_t)out_size) out[fo] = (s > 0) ? 1.f : 0.f;
    }
    snrm[tid] = nrm;
    slabel[tid] = lab;
    __syncthreads();

    int j0 = blockIdx.x * 256;
    int nanch = NL - j0; if (nanch > 256) nanch = 256;
    if (nanch <= 0) return;
    size_t base = (size_t)5 * BL + ((size_t)b * NL + j0) * NC;
    int total4 = nanch * (NC / 4);
    float4* ob = (float4*)(out + base);
    for (int f = tid; f < total4; f += 256) {
        int a = f / (NC / 4);
        int c0 = (f % (NC / 4)) * 4;
        float4 w = {0.f, 0.f, 0.f, 0.f};
        int L = slabel[a];
        if (L >= c0 && L < c0 + 4) ((float*)&w)[L - c0] = snrm[a];
        if (base + (size_t)f * 4 + 3 < (size_t)out_size) ob[f] = w;
    }
}

// ---------------- launch ----------------
extern "C" void kernel_launch(void* const* d_in, const int* in_sizes, int n_in,
                              void* d_out, int out_size) {
    const float* pred_scores = (const float*)d_in[0];
    const float* pred_bboxes = (const float*)d_in[1];
    const float* centers     = (const float*)d_in[2];
    const int*   gt_labels   = (const int*)d_in[3];
    const float* gt_bboxes   = (const float*)d_in[4];
    const float* pad         = (const float*)d_in[5];
    float* out = (float*)d_out;

    dim3 grid2d((NL + 255) / 256, NB);
    k_pair<<<grid2d, 256>>>(pred_scores, pred_bboxes, centers,
                            gt_labels, gt_bboxes, pad);
    k_topk<<<NB * NGT, 256>>>(pad);
    k_fix<<<(NSEL + 255) / 256, 256>>>(pred_scores, pred_bboxes, centers,
                                       gt_labels, gt_bboxes, pad);
    k_out<<<grid2d, 256>>>(pred_scores, pred_bboxes, centers,
                           gt_labels, gt_bboxes, out, out_size);
}

// round 8
// speedup vs baseline: 1.5229x; 1.0527x over previous
#include <cuda_runtime.h>
#include <math.h>
#include <stdint.h>

#define NB 32
#define NL 8400
#define NC 80
#define NGT 64
#define KTOP 13
#define CAP 2048
#define NW 263              /* ceil(8400/32) */
#define NSEL (NB * NGT * KTOP)
#define FEPS 1e-9f
#define CEPS 1e-7f
#define BL (NB * NL)

// ---------------- device scratch (static zero-init; pipeline self-cleans) ----------------
__device__ unsigned long long g_ckey[(size_t)NB * NGT * CAP]; // row-sparse candidate keys
__device__ unsigned int g_cnt[NB * NGT];                      // per-row candidate counts
__device__ unsigned int g_colmax[BL];                         // per-anchor max iou bits
__device__ unsigned long long g_posmask[BL];                  // per-anchor positive gt bits
__device__ unsigned int g_rowmaxM[NB * NGT];                  // float bits, >=0
__device__ unsigned int g_rowmaxI[NB * NGT];
__device__ int g_selidx[NSEL];                                // anchor+1 per (row,k), 0=empty

// ---- shared noinline math: ONE code body -> bit-identical across kernels ----
__device__ __noinline__ float atan_ratio(float w, float h) {
    return atanf(__fdividef(w, h));
}

__device__ __noinline__ float ciou_clip(float4 gb, float4 p, float gatan, float patan) {
    const float c4pi2 = 4.0f / (float)(M_PI * M_PI);
    float a1 = (gb.z - gb.x) * (gb.w - gb.y);
    float a2 = (p.z - p.x) * (p.w - p.y);
    float iw = fminf(gb.z, p.z) - fmaxf(gb.x, p.x);
    float ih = fminf(gb.w, p.w) - fmaxf(gb.y, p.y);
    float inter = fmaxf(iw, 0.f) * fmaxf(ih, 0.f);
    float uni = a1 + a2 - inter;
    float iou = __fdividef(inter, uni);
    float cw = fmaxf(fmaxf(gb.z, p.z) - fminf(gb.x, p.x), 0.f);
    float ch = fmaxf(fmaxf(gb.w, p.w) - fminf(gb.y, p.y), 0.f);
    float diag2 = cw * cw + ch * ch + CEPS;
    float dx = (gb.x + gb.z) * 0.5f - (p.x + p.z) * 0.5f;
    float dy = (gb.y + gb.w) * 0.5f - (p.y + p.w) * 0.5f;
    float diou = iou - __fdividef(dx * dx + dy * dy, diag2);
    float dv = gatan - patan;
    float v = c4pi2 * dv * dv;
    float ciou = diou - __fdividef(v * v, 1.f - iou + v + CEPS);
    return fmaxf(ciou, 0.f);
}

// ---------------- kernel 1: candidates + colmax + ALL default outputs ----------------
__global__ void __launch_bounds__(256) k_pair(
        const float* __restrict__ pred_scores,
        const float* __restrict__ pred_bboxes,
        const float* __restrict__ centers,
        const int* __restrict__ gt_labels,
        const float* __restrict__ gt_bboxes,
        const float* __restrict__ pad,
        float* __restrict__ out, int out_size) {
    int b = blockIdx.y;
    int tid = threadIdx.x;
    int j = blockIdx.x * 256 + tid;
    int lane = tid & 31;
    unsigned lmask_lt = (1u << lane) - 1u;

    __shared__ float4 sbox[NGT];
    __shared__ int slab[NGT];
    __shared__ float satan[NGT];
    __shared__ int scnt;

    if (tid < NGT) {
        float4 gb = ((const float4*)gt_bboxes)[b * NGT + tid];
        sbox[tid] = gb;
        slab[tid] = gt_labels[b * NGT + tid];
        satan[tid] = atan_ratio(gb.z - gb.x, gb.w - gb.y);
    }
    if (tid == 0) {
        int c = 0;
        for (int i = 0; i < NGT; i++) c += (pad[b * NGT + i] != 0.f);
        scnt = c;
    }
    __syncthreads();

    int cnt = scnt;
    bool live = (j < NL);
    int jc = live ? j : (NL - 1);

    float2 ct = ((const float2*)centers)[jc];
    float4 p = ((const float4*)pred_bboxes)[(size_t)b * NL + jc];
    float patan = atan_ratio(p.z - p.x, p.w - p.y);
    const float* srow = pred_scores + ((size_t)b * NL + jc) * NC;

    float colmax = 0.f;
    for (int i = 0; i < cnt; i++) {
        float4 gb = sbox[i];
        float lt = fminf(fminf(ct.x - gb.x, ct.y - gb.y),
                         fminf(gb.z - ct.x, gb.w - ct.y));
        bool in = live && (lt > FEPS);
        unsigned m = __ballot_sync(0xFFFFFFFFu, in);
        if (!m) continue;
        unsigned long long key = 0ull;
        if (in) {
            float io = ciou_clip(gb, p, satan[i], patan);
            colmax = fmaxf(colmax, io);
            float score = __ldg(srow + slab[i]);
            float m2 = io * io;
            float m6 = m2 * m2 * m2;
            float metric = score * m6;
            key = ((unsigned long long)__float_as_uint(metric) << 32) |
                  (unsigned long long)(0xFFFFFFFFu - (unsigned)j);
        }
        int row = b * NGT + i;
        int leader = __ffs(m) - 1;
        unsigned base = 0;
        if (lane == leader) base = atomicAdd(&g_cnt[row], (unsigned)__popc(m));
        base = __shfl_sync(0xFFFFFFFFu, base, leader);
        if (in) {
            unsigned pos = base + (unsigned)__popc(m & lmask_lt);
            if (pos < CAP) g_ckey[(size_t)row * CAP + pos] = key;
        }
    }

    if (live) {
        int t = b * NL + j;
        g_colmax[t] = __float_as_uint(colmax);
        g_posmask[t] = 0ull;
        // default scalar outputs: label=BG, bbox=gt box 0, fg=0
        if (t < out_size) out[t] = (float)NC;
        size_t bo = (size_t)BL + (size_t)t * 4;
        if (bo + 3 < (size_t)out_size)
            ((float4*)(out + BL))[t] = sbox[0];
        size_t fo = (size_t)85 * BL + t;
        if (fo < (size_t)out_size) out[fo] = 0.f;
    }

    // default scores: zeros (coalesced block-cooperative float4 stream)
    int j0 = blockIdx.x * 256;
    int nanch = NL - j0; if (nanch > 256) nanch = 256;
    if (nanch <= 0) return;
    size_t base = (size_t)5 * BL + ((size_t)b * NL + j0) * NC;
    int total4 = nanch * (NC / 4);
    float4* ob = (float4*)(out + base);
    const float4 z = {0.f, 0.f, 0.f, 0.f};
    for (int f = tid; f < total4; f += 256)
        if (base + (size_t)f * 4 + 3 < (size_t)out_size) ob[f] = z;
}

// ---------------- kernel 2: top-13 per row -> posmask bits + per-row slot list ----------------
__global__ void __launch_bounds__(256) k_topk(const float* __restrict__ pad) {
    int gt = blockIdx.x;
    if (pad[gt] == 0.f) return;
    int b = gt >> 6;
    int i = gt & 63;
    int t = threadIdx.x;

    __shared__ unsigned long long sh[256][KTOP];
    __shared__ unsigned scand[NW];
    __shared__ unsigned szcand[NW];
    __shared__ int semit[KTOP];

    for (int w = t; w < NW; w += 256) { scand[w] = 0u; szcand[w] = 0u; }
    if (t == 0) {                       // self-clean rowmax for this row
        g_rowmaxM[gt] = 0u;
        g_rowmaxI[gt] = 0u;
    }
    __syncthreads();

    unsigned count = g_cnt[gt];
    if (count > CAP) count = CAP;
    const unsigned long long* keys = g_ckey + (size_t)gt * CAP;

    unsigned long long best[KTOP];
#pragma unroll
    for (int k = 0; k < KTOP; k++) best[k] = 0ull;

    for (unsigned c = t; c < count; c += 256) {
        unsigned long long key = keys[c];
        unsigned j = 0xFFFFFFFFu - (unsigned)(key & 0xFFFFFFFFull);
        atomicOr(&scand[j >> 5], 1u << (j & 31));
        if ((unsigned)(key >> 32) == 0u)
            atomicOr(&szcand[j >> 5], 1u << (j & 31));
        if (key > best[KTOP - 1]) {
            best[KTOP - 1] = key;
#pragma unroll
            for (int q = KTOP - 1; q > 0; q--) {
                if (best[q] > best[q - 1]) {
                    unsigned long long tmp = best[q - 1];
                    best[q - 1] = best[q]; best[q] = tmp;
                }
            }
        }
    }
#pragma unroll
    for (int k = 0; k < KTOP; k++) sh[t][k] = best[k];
    __syncthreads();

    for (int s = 128; s > 0; s >>= 1) {
        if (t < s) {
            unsigned long long tmp[KTOP];
            int a = 0, c = 0;
#pragma unroll
            for (int k = 0; k < KTOP; k++) {
                unsigned long long va = sh[t][a];
                unsigned long long vb = sh[t + s][c];
                if (va >= vb) { tmp[k] = va; a++; }
                else          { tmp[k] = vb; c++; }
            }
#pragma unroll
            for (int k = 0; k < KTOP; k++) sh[t][k] = tmp[k];
        }
        __syncthreads();
    }

    // positive-metric selections: posmask bits + slot entries
    if (t < KTOP) {
        unsigned long long key = sh[0][t];
        int sel = 0;
        if ((unsigned)(key >> 32) != 0u) {
            unsigned j = 0xFFFFFFFFu - (unsigned)(key & 0xFFFFFFFFull);
            int anc = b * NL + (int)j;
            atomicOr(&g_posmask[anc], 1ull << i);
            sel = anc + 1;
        }
        semit[t] = sel;
    }
    if (t == 0) g_cnt[gt] = 0u;         // self-clean candidate counter
    __syncthreads();

    if (t == 0) {
        // jax zero-fill: smallest indices with metric==0 (zero candidate OR
        // non-candidate); only zero-metric candidates (in_gts=1) emit bits.
        int need = 0;
#pragma unroll
        for (int k = 0; k < KTOP; k++) need += (semit[k] == 0);
        int slot = 0;
        for (int w = 0; w < NW && need > 0; w++) {
            unsigned zm = (~scand[w]) | szcand[w];
            if (w == NW - 1) zm &= 0xFFFFu;  // 8400 = 262*32 + 16
            while (zm && need > 0) {
                int bit = __ffs(zm) - 1;
                zm &= zm - 1;
                need--;
                if ((szcand[w] >> bit) & 1u) {
                    int anc = b * NL + w * 32 + bit;
                    atomicOr(&g_posmask[anc], 1ull << i);
                    while (semit[slot] != 0) slot++;
                    semit[slot] = anc + 1;
                }
            }
        }
    }
    __syncthreads();
    if (t < KTOP) g_selidx[gt * KTOP + t] = semit[t];
}

// ---------------- kernel 3: fixup + rowmax over selected anchors (dups harmless) ----------------
__global__ void __launch_bounds__(256) k_fix(
        const float* __restrict__ pred_scores,
        const float* __restrict__ pred_bboxes,
        const float* __restrict__ centers,
        const int* __restrict__ gt_labels,
        const float* __restrict__ gt_bboxes,
        const float* __restrict__ pad) {
    int k = blockIdx.x * 256 + threadIdx.x;
    if (k >= NSEL) return;
    int sel = g_selidx[k];
    if (sel == 0) return;
    int t = sel - 1;
    int b = t / NL;
    int j = t - b * NL;

    unsigned long long pm = g_posmask[t];
    int s = __popcll(pm);

    float2 ct = ((const float2*)centers)[j];
    float4 p = ((const float4*)pred_bboxes)[(size_t)b * NL + j];
    float patan = atan_ratio(p.z - p.x, p.w - p.y);
    const float* srow = pred_scores + ((size_t)b * NL + j) * NC;

    if (s > 1) {
        float mx = __uint_as_float(g_colmax[t]);
        if (mx == 0.f) {
            pm = 1ull;              // all-zero column: argmax=0, zero terms downstream
        } else {
            int cnt = 0;
            for (int i = 0; i < NGT; i++) cnt += (pad[b * NGT + i] != 0.f);
            pm = 0ull;
            for (int i = 0; i < cnt; i++) {
                float4 gb = ((const float4*)gt_bboxes)[b * NGT + i];
                float lt = fminf(fminf(ct.x - gb.x, ct.y - gb.y),
                                 fminf(gb.z - ct.x, gb.w - ct.y));
                if (lt > FEPS) {
                    float gatan = atan_ratio(gb.z - gb.x, gb.w - gb.y);
                    float io = ciou_clip(gb, p, gatan, patan);
                    if (io == mx) pm |= 1ull << i;
                }
            }
        }
        g_posmask[t] = pm;
    }

    unsigned long long q = pm;
    while (q) {
        int i = __ffsll(q) - 1;
        q &= q - 1;
        float4 gb = ((const float4*)gt_bboxes)[b * NGT + i];
        float lt = fminf(fminf(ct.x - gb.x, ct.y - gb.y),
                         fminf(gb.z - ct.x, gb.w - ct.y));
        float io = 0.f, metric = 0.f;
        if (lt > FEPS) {
            float gatan = atan_ratio(gb.z - gb.x, gb.w - gb.y);
            io = ciou_clip(gb, p, gatan, patan);
            float score = __ldg(srow + gt_labels[b * NGT + i]);
            float m2 = io * io;
            float m6 = m2 * m2 * m2;
            metric = score * m6;
        }
        atomicMax(&g_rowmaxM[b * NGT + i], __float_as_uint(metric));
        atomicMax(&g_rowmaxI[b * NGT + i], __float_as_uint(io));
    }
}

// ---------------- kernel 4: sparse finalize of positive anchors ----------------
__global__ void __launch_bounds__(256) k_out(
        const float* __restrict__ pred_scores,
        const float* __restrict__ pred_bboxes,
        const float* __restrict__ centers,
        const int* __restrict__ gt_labels,
        const float* __restrict__ gt_bboxes,
        float* __restrict__ out, int out_size) {
    int k = blockIdx.x * 256 + threadIdx.x;
    if (k >= NSEL) return;
    int sel = g_selidx[k];
    if (sel == 0) return;
    int t = sel - 1;
    int b = t / NL;
    int j = t - b * NL;

    unsigned long long pm = g_posmask[t];   // after fix: nonzero
    int ag0 = __ffsll(pm) - 1;
    int lab = gt_labels[b * NGT + ag0];

    float2 ct = ((const float2*)centers)[j];
    float4 p = ((const float4*)pred_bboxes)[(size_t)b * NL + j];
    float patan = atan_ratio(p.z - p.x, p.w - p.y);
    const float* srow = pred_scores + ((size_t)b * NL + j) * NC;

    float nrm = 0.f;
    unsigned long long q = pm;
    while (q) {
        int i = __ffsll(q) - 1;
        q &= q - 1;
        float4 gb = ((const float4*)gt_bboxes)[b * NGT + i];
        float lt = fminf(fminf(ct.x - gb.x, ct.y - gb.y),
                         fminf(gb.z - ct.x, gb.w - ct.y));
        if (lt > FEPS) {
            float gatan = atan_ratio(gb.z - gb.x, gb.w - gb.y);
            float io = ciou_clip(gb, p, gatan, patan);
            float score = __ldg(srow + gt_labels[b * NGT + i]);
            float m2 = io * io;
            float m6 = m2 * m2 * m2;
            float metric = score * m6;
            float term = __fdividef(metric,
                             __uint_as_float(g_rowmaxM[b * NGT + i]) + FEPS) *
                         __uint_as_float(g_rowmaxI[b * NGT + i]);
            nrm = fmaxf(nrm, term);
        }
    }

    // overwrite defaults (duplicate threads write identical values)
    if (t < out_size) out[t] = (float)lab;
    size_t bo = (size_t)BL + (size_t)t * 4;
    if (bo + 3 < (size_t)out_size)
        ((float4*)(out + BL))[t] = ((const float4*)gt_bboxes)[b * NGT + ag0];
    size_t fo = (size_t)85 * BL + t;
    if (fo < (size_t)out_size) out[fo] = 1.f;
    size_t so = (size_t)5 * BL + (size_t)t * NC + lab;
    if (so < (size_t)out_size) out[so] = nrm;
}

// ---------------- launch ----------------
extern "C" void kernel_launch(void* const* d_in, const int* in_sizes, int n_in,
                              void* d_out, int out_size) {
    const float* pred_scores = (const float*)d_in[0];
    const float* pred_bboxes = (const float*)d_in[1];
    const float* centers     = (const float*)d_in[2];
    const int*   gt_labels   = (const int*)d_in[3];
    const float* gt_bboxes   = (const float*)d_in[4];
    const float* pad         = (const float*)d_in[5];
    float* out = (float*)d_out;

    dim3 grid2d((NL + 255) / 256, NB);
    k_pair<<<grid2d, 256>>>(pred_scores, pred_bboxes, centers,
                            gt_labels, gt_bboxes, pad, out, out_size);
    k_topk<<<NB * NGT, 256>>>(pad);
    k_fix<<<(NSEL + 255) / 256, 256>>>(pred_scores, pred_bboxes, centers,
                                       gt_labels, gt_bboxes, pad);
    k_out<<<(NSEL + 255) / 256, 256>>>(pred_scores, pred_bboxes, centers,
                                       gt_labels, gt_bboxes, out, out_size);
}